// round 11
// baseline (speedup 1.0000x reference)
#include <cuda_runtime.h>
#include <cuda_fp16.h>

// ---------------------------------------------------------------------------
// Collapsed TemporalGNN (H0 == 0 in the scan; R gate dead):
//   y_d  = dinv_d * ( xT'_d + sum_{s in bkt(d)} xT'_s ),  xT'_n = dinv_n * x_n
//   Hn   = (1 + tanh(-(y@Mz + cz)/2)) * tanh(y@Mh + ch) * 0.5
//   acc  = sum_t p_t * Hn ;  out = relu(acc) @ head_w + head_b
// deg = cnt + 1 (self loops). Fork-join graph:
//   stream0: k_fill (buckets+g_cnt) ------------> k_gather -> k_node
//   streamB: k_count (g_cnt2) -> k_trans (xT') --^             ^
//   streamC: k_wts --------------------------------------------|
// xT has a reserved all-zero row (index NN) used to mask ragged bucket tails,
// so the gather loop is conditional-free pure shuffles+loads+adds.
// g_cnt/g_cnt2 start zeroed (module load), re-zeroed by k_node each call.
// ---------------------------------------------------------------------------

#define NB 4
#define NT 12
#define NN 30000
#define NH 32
#define NO 12
#define NE 240000
#define NODE_W 24               /* F_IN(2) * T(12) floats per (b,node) */
#define NQ (NODE_W / 4)
#define CAP 64
#define FILL_BLOCKS ((NE + 255) / 256)
#define TRQ (NB * NN * NQ)      /* 720000 float4 to transpose */
#define TR_THREADS (TRQ / 2)    /* 2 float4 per thread */
#define TR_BLOCKS ((TR_THREADS + 255) / 256)

typedef unsigned long long u64;

__device__ int      g_cnt[NN];                    // fill cursor == in-degree
__device__ int      g_cnt2[NN];                   // count-only (for trans)
__device__ unsigned g_bkt[(size_t)NN * CAP];      // src ids
__device__ float g_xT[(size_t)(NN + 1) * NB * NODE_W];  // row NN: always zero
__device__ float g_y[(size_t)NB * NN * NODE_W];   // batch-major aggregated
__device__ float g_Mz[2 * NH];                    // NEGATED, x0.5
__device__ float g_Mh[2 * NH];
__device__ float g_cz[NH];                        // NEGATED, x0.5
__device__ float g_ch[NH];
__device__ float g_p[NT];                         // softmax * 0.5

// ---- packed-math helpers ----
__device__ __forceinline__ u64 pk(float lo, float hi) {
    u64 r; asm("mov.b64 %0, {%1, %2};" : "=l"(r) : "f"(lo), "f"(hi)); return r;
}
__device__ __forceinline__ void upk(u64 v, float& lo, float& hi) {
    asm("mov.b64 {%0, %1}, %2;" : "=f"(lo), "=f"(hi) : "l"(v));
}
__device__ __forceinline__ u64 fma2(u64 a, u64 b, u64 c) {
    u64 r; asm("fma.rn.f32x2 %0, %1, %2, %3;" : "=l"(r) : "l"(a), "l"(b), "l"(c));
    return r;
}
__device__ __forceinline__ unsigned cvt2(float lo, float hi) {   // -> f16x2
    unsigned r; asm("cvt.rn.f16x2.f32 %0, %1, %2;" : "=r"(r) : "f"(hi), "f"(lo));
    return r;
}
__device__ __forceinline__ unsigned tanh2(unsigned x) {
    unsigned r; asm("tanh.approx.f16x2 %0, %1;" : "=r"(r) : "r"(x)); return r;
}
__device__ __forceinline__ unsigned hfma2u(unsigned a, unsigned b, unsigned c) {
    unsigned r; asm("fma.rn.f16x2 %0, %1, %2, %3;" : "=r"(r) : "r"(a), "r"(b), "r"(c));
    return r;
}

// Edge fill: push src into dst's bucket (g_cnt is the slot cursor).
__global__ void k_fill(const int* __restrict__ ei) {
    int e = blockIdx.x * 256 + threadIdx.x;
    if (e >= NE) return;
    int s = __ldg(ei + e);
    int d = __ldg(ei + NE + e);
    int pos = atomicAdd(&g_cnt[d], 1);
    g_bkt[(size_t)d * CAP + pos] = (unsigned)s;
}

// Count-only pass (independent array -> runs concurrently with k_fill).
__global__ void k_count(const int* __restrict__ ei) {
    int e = blockIdx.x * 256 + threadIdx.x;
    if (e < NE) atomicAdd(&g_cnt2[ei[NE + e]], 1);
}

// Transpose + pre-scale: xT'[n][b][.] = rsqrt(cnt2[n]+1) * x[b][n][.].
__global__ void k_trans(const float* __restrict__ x) {
    int tid = blockIdx.x * 256 + threadIdx.x;
    if (tid >= TR_THREADS) return;
#pragma unroll
    for (int half = 0; half < 2; half++) {
        int i = tid + half * TR_THREADS;          // float4 id in xT order
        int q = i % NQ;
        int b = (i / NQ) & 3;
        int n = i / (NQ * NB);
        float dinv = rsqrtf((float)(g_cnt2[n] + 1));
        float4 v = __ldg((const float4*)x + ((size_t)b * NN + n) * NQ + q);
        v.x *= dinv; v.y *= dinv; v.z *= dinv; v.w *= dinv;
        ((float4*)g_xT)[i] = v;
    }
}

// Fused weights + softmax. One block.
__global__ void k_wts(const float* __restrict__ att,
                      const float* __restrict__ czw, const float* __restrict__ czb,
                      const float* __restrict__ lzw, const float* __restrict__ lzb,
                      const float* __restrict__ chw, const float* __restrict__ chb,
                      const float* __restrict__ lhw, const float* __restrict__ lhb) {
    int lane = threadIdx.x & 31;
    int warp = threadIdx.x >> 5;
    if (threadIdx.x == 0) {
        float m = -1e30f;
        for (int i = 0; i < NT; i++) m = fmaxf(m, att[i]);
        float e[NT], s = 0.f;
        for (int i = 0; i < NT; i++) { e[i] = __expf(att[i] - m); s += e[i]; }
        float inv = 0.5f / s;                    // fold the 0.5 of (1-tz)/2 here
        for (int i = 0; i < NT; i++) g_p[i] = e[i] * inv;
    }
#pragma unroll
    for (int i = warp; i < 2 * NH; i += 8) {
        int gate = i >> 5;                       // 0 = z gate, 1 = h gate
        int h = i & 31;
        const float* cw = gate ? chw : czw;
        const float* cb = gate ? chb : czb;
        const float* lw = gate ? lhw : lzw;
        const float* lb = gate ? lhb : lzb;
        float w = lw[lane * NH + h];             // only first NH rows matter (H0=0)
        float m0 = cw[lane] * w;
        float m1 = cw[NH + lane] * w;
        float c  = cb[lane] * w;
#pragma unroll
        for (int off = 16; off; off >>= 1) {
            m0 += __shfl_xor_sync(0xffffffffu, m0, off);
            m1 += __shfl_xor_sync(0xffffffffu, m1, off);
            c  += __shfl_xor_sync(0xffffffffu, c, off);
        }
        if (lane == 0) {
            c += lb[h];
            if (gate == 0) {                     // negate: tanh(-az/2) = -tz
                g_Mz[h] = -0.5f * m0; g_Mz[NH + h] = -0.5f * m1; g_cz[h] = -0.5f * c;
            } else {
                g_Mh[h] = m0; g_Mh[NH + h] = m1; g_ch[h] = c;
            }
        }
    }
}

// Gather: one warp per node, all 4 batches. 2-level prologue (cnt -> bucket),
// NO per-edge norms: xT' rows are pre-scaled by dinv_src; final scale dinv_d.
// Ragged tails point at the all-zero row NN -> pure adds, no conditionals.
__global__ void __launch_bounds__(256)
k_gather() {
    int n    = blockIdx.x * 8 + (threadIdx.x >> 5);   // NN % 8 == 0
    int lane = threadIdx.x & 31;

    int   cnt  = g_cnt[n];
    float dinv = rsqrtf((float)(cnt + 1));            // deg = cnt + 1
    const unsigned* brow = g_bkt + (size_t)n * CAP;

    unsigned s0 = (lane < cnt) ? brow[lane] : (unsigned)NN;  // NN = zero row

    bool act = lane < 24;
    const float4* xT4 = (const float4*)g_xT;

    float4 acc = make_float4(0.f, 0.f, 0.f, 0.f);
    if (act) acc = __ldg(xT4 + (size_t)n * 24 + lane);       // self: xT'_d

    if (cnt <= 32) {
        int rc = (cnt + 7) >> 3;                      // 8-edge groups
        for (int g = 0; g < rc; g++) {
            int e = 8 * g;
            unsigned c_[8];
#pragma unroll
            for (int i = 0; i < 8; i++)
                c_[i] = __shfl_sync(0xffffffffu, s0, e + i);
            if (act) {
                float4 v[8];
#pragma unroll
                for (int i = 0; i < 8; i++)
                    v[i] = __ldg(xT4 + (size_t)c_[i] * 24 + lane);
#pragma unroll
                for (int i = 0; i < 8; i++) {
                    acc.x += v[i].x; acc.y += v[i].y;
                    acc.z += v[i].z; acc.w += v[i].w;
                }
            }
        }
    } else {
        // Generic fallback (in-degree > 32): lane-uniform per-edge loop.
        for (int e = 0; e < cnt; e++) {
            unsigned c = brow[e];
            if (act) {
                float4 v = __ldg(xT4 + (size_t)c * 24 + lane);
                acc.x += v.x; acc.y += v.y; acc.z += v.z; acc.w += v.w;
            }
        }
    }
    if (act) {
        acc.x *= dinv; acc.y *= dinv; acc.z *= dinv; acc.w *= dinv;
        int q = lane % 6, b = lane / 6;
        ((float4*)g_y)[((size_t)b * NN + n) * NQ + q] = acc;
    }
}

// Pointwise collapse + head GEMV. One thread per (b, node).
// First blocks also re-zero both count arrays for the next graph replay.
__global__ void __launch_bounds__(256)
k_node(const float* __restrict__ hw, const float* __restrict__ hb,
       float* __restrict__ out) {
    __shared__ u64 s_Mz0[16], s_Mz1[16], s_czp[16];
    __shared__ u64 s_Mh0[16], s_Mh1[16], s_chp[16];
    __shared__ u64 s_hwp[NH * NO / 2];
    __shared__ u64 s_hbp[NO / 2];
    __shared__ unsigned s_ph[NT];
    int tid = threadIdx.x;
    int gid = blockIdx.x * 256 + tid;

    if (gid < NN) { g_cnt[gid] = 0; g_cnt2[gid] = 0; }   // reset for replay

    if (tid < 16) {
        s_Mz0[tid] = pk(g_Mz[2 * tid], g_Mz[2 * tid + 1]);
        s_Mz1[tid] = pk(g_Mz[NH + 2 * tid], g_Mz[NH + 2 * tid + 1]);
        s_czp[tid] = pk(g_cz[2 * tid], g_cz[2 * tid + 1]);
        s_Mh0[tid] = pk(g_Mh[2 * tid], g_Mh[2 * tid + 1]);
        s_Mh1[tid] = pk(g_Mh[NH + 2 * tid], g_Mh[NH + 2 * tid + 1]);
        s_chp[tid] = pk(g_ch[2 * tid], g_ch[2 * tid + 1]);
    }
    if (tid < NT) {
        __half2 h2 = __float2half2_rn(g_p[tid]);
        s_ph[tid] = *(unsigned*)&h2;
    }
    for (int i = tid; i < NH * NO / 2; i += 256) s_hwp[i] = ((const u64*)hw)[i];
    if (tid < NO / 2) s_hbp[tid] = ((const u64*)hb)[tid];
    __syncthreads();

    if (gid >= NB * NN) return;

    float yv[NODE_W];
    const float4* yp4 = (const float4*)(g_y + (size_t)gid * NODE_W);
#pragma unroll
    for (int i = 0; i < NQ; i++) {
        float4 v = yp4[i];
        yv[4 * i] = v.x; yv[4 * i + 1] = v.y; yv[4 * i + 2] = v.z; yv[4 * i + 3] = v.w;
    }
    u64 a2[NT], b2[NT];
#pragma unroll
    for (int t = 0; t < NT; t++) { a2[t] = pk(yv[t], yv[t]); b2[t] = pk(yv[NT + t], yv[NT + t]); }
    unsigned ph_[NT];
#pragma unroll
    for (int t = 0; t < NT; t++) ph_[t] = s_ph[t];

    u64 o2[NO / 2];
#pragma unroll
    for (int j = 0; j < NO / 2; j++) o2[j] = s_hbp[j];

#pragma unroll 1
    for (int k = 0; k < 16; k++) {                // h-pair index
        u64 mz0 = s_Mz0[k], mz1 = s_Mz1[k], czc = s_czp[k];
        u64 mh0 = s_Mh0[k], mh1 = s_Mh1[k], chc = s_chp[k];
        unsigned acc = 0;                         // half2 zero
#pragma unroll
        for (int t = 0; t < NT; t++) {
            u64 azn = fma2(a2[t], mz0, fma2(b2[t], mz1, czc));  // = -(az)/2 pair
            u64 ahp = fma2(a2[t], mh0, fma2(b2[t], mh1, chc));
            float zl, zh, hl, hh;
            upk(azn, zl, zh); upk(ahp, hl, hh);
            unsigned tzn = tanh2(cvt2(zl, zh));   // = -tz (odd fn, consts negated)
            unsigned th  = tanh2(cvt2(hl, hh));
            unsigned u   = hfma2u(tzn, th, th);   // (1 - tz) * th
            acc = hfma2u(ph_[t], u, acc);
        }
        __half2 ah2 = *(__half2*)&acc;
        float rl = fmaxf(__low2float(ah2), 0.f);  // relu, h = 2k
        float rh = fmaxf(__high2float(ah2), 0.f); // h = 2k+1
        u64 rl2 = pk(rl, rl), rh2 = pk(rh, rh);
        const u64* w0 = &s_hwp[(2 * k) * (NO / 2)];
        const u64* w1 = &s_hwp[(2 * k + 1) * (NO / 2)];
#pragma unroll
        for (int j = 0; j < NO / 2; j++)
            o2[j] = fma2(rl2, w0[j], fma2(rh2, w1[j], o2[j]));
    }

    float of[NO];
#pragma unroll
    for (int j = 0; j < NO / 2; j++) upk(o2[j], of[2 * j], of[2 * j + 1]);
    float4* op4 = (float4*)(out + (size_t)gid * NO);
#pragma unroll
    for (int j = 0; j < NO / 4; j++)
        op4[j] = make_float4(of[4 * j], of[4 * j + 1], of[4 * j + 2], of[4 * j + 3]);
}

extern "C" void kernel_launch(void* const* d_in, const int* in_sizes, int n_in,
                              void* d_out, int out_size) {
    const float* x   = (const float*)d_in[0];
    const int*   ei  = (const int*)d_in[1];
    const float* att = (const float*)d_in[2];
    const float* czw = (const float*)d_in[3];
    const float* czb = (const float*)d_in[4];
    const float* lzw = (const float*)d_in[5];
    const float* lzb = (const float*)d_in[6];
    // d_in[7..10] = conv_r_*, lin_r_* : dead (H0 == 0 -> H0*R == 0)
    const float* chw = (const float*)d_in[11];
    const float* chb = (const float*)d_in[12];
    const float* lhw = (const float*)d_in[13];
    const float* lhb = (const float*)d_in[14];
    const float* hw  = (const float*)d_in[15];
    const float* hb  = (const float*)d_in[16];
    float* out = (float*)d_out;

    // Host-side resources created once on the first (uncaptured correctness)
    // call. Device work per call is identical -> deterministic & capturable.
    static cudaStream_t sB = nullptr, sC = nullptr;
    static cudaEvent_t eF = nullptr, eB = nullptr, eC = nullptr;
    if (sB == nullptr) {
        cudaStreamCreateWithFlags(&sB, cudaStreamNonBlocking);
        cudaStreamCreateWithFlags(&sC, cudaStreamNonBlocking);
        cudaEventCreateWithFlags(&eF, cudaEventDisableTiming);
        cudaEventCreateWithFlags(&eB, cudaEventDisableTiming);
        cudaEventCreateWithFlags(&eC, cudaEventDisableTiming);
    }

    // Fork: bring side streams into the capture graph.
    cudaEventRecord(eF, 0);
    cudaStreamWaitEvent(sB, eF, 0);
    cudaStreamWaitEvent(sC, eF, 0);

    k_fill<<<FILL_BLOCKS, 256>>>(ei);                       // stream 0
    k_count<<<FILL_BLOCKS, 256, 0, sB>>>(ei);               // stream B
    k_trans<<<TR_BLOCKS, 256, 0, sB>>>(x);                  // stream B (after count)
    k_wts<<<1, 256, 0, sC>>>(att, czw, czb, lzw, lzb,
                             chw, chb, lhw, lhb);           // stream C

    // Join B before gather (needs buckets + pre-scaled xT).
    cudaEventRecord(eB, sB);
    cudaStreamWaitEvent(0, eB, 0);
    k_gather<<<NN / 8, 256>>>();

    // Join C before node (needs fused weights).
    cudaEventRecord(eC, sC);
    cudaStreamWaitEvent(0, eC, 0);
    k_node<<<(NB * NN + 255) / 256, 256>>>(hw, hb, out);
}

// round 12
// speedup vs baseline: 1.0727x; 1.0727x over previous
#include <cuda_runtime.h>
#include <cuda_fp16.h>

// ---------------------------------------------------------------------------
// Collapsed TemporalGNN (H0 == 0 in the scan; R gate dead):
//   y    = A_hat x           (pull-gather via per-dst buckets, no atomics)
//   Hn   = (1 + tanh(-(y@Mz + cz)/2)) * tanh(y@Mh + ch) * 0.5
//   acc  = sum_t p_t * Hn ;  out = relu(acc) @ head_w + head_b
// deg = cnt + 1 (self loops). Fork-join graph (R10 structure):
//   stream0: k_fill (buckets+g_cnt) -> k_gather -> k_node
//   streamB: k_trans (x -> f16 xT[n][b][24]) --^      ^
//   streamC: k_wts ------------------------------------|
// xT staged in f16 (192B/node row): halves gather bytes AND L2 lines/edge.
// Accumulation stays f32; per-edge norms from g_cnt[src] in the prologue.
// g_cnt starts zeroed (module load) and is re-zeroed by k_node each call.
// ---------------------------------------------------------------------------

#define NB 4
#define NT 12
#define NN 30000
#define NH 32
#define NO 12
#define NE 240000
#define NODE_W 24               /* F_IN(2) * T(12) floats per (b,node) */
#define NQ (NODE_W / 4)
#define CAP 64
#define FILL_BLOCKS ((NE + 255) / 256)
#define TRQ (NB * NN * NQ)      /* 720000 quad-groups to transpose */
#define TR_THREADS (TRQ / 2)    /* 2 quads per thread */
#define TR_BLOCKS ((TR_THREADS + 255) / 256)

typedef unsigned long long u64;

__device__ int      g_cnt[NN];                    // zero-init; re-zeroed by k_node
__device__ unsigned g_bkt[(size_t)NN * CAP];      // src ids
__device__ __half   g_xTh[(size_t)NN * NB * NODE_W];  // f16 node-major x (192B/row)
__device__ float g_y[(size_t)NB * NN * NODE_W];   // batch-major aggregated (f32)
__device__ float g_Mz[2 * NH];                    // NEGATED, x0.5
__device__ float g_Mh[2 * NH];
__device__ float g_cz[NH];                        // NEGATED, x0.5
__device__ float g_ch[NH];
__device__ float g_p[NT];                         // softmax * 0.5

// ---- packed-math helpers ----
__device__ __forceinline__ u64 pk(float lo, float hi) {
    u64 r; asm("mov.b64 %0, {%1, %2};" : "=l"(r) : "f"(lo), "f"(hi)); return r;
}
__device__ __forceinline__ void upk(u64 v, float& lo, float& hi) {
    asm("mov.b64 {%0, %1}, %2;" : "=f"(lo), "=f"(hi) : "l"(v));
}
__device__ __forceinline__ u64 fma2(u64 a, u64 b, u64 c) {
    u64 r; asm("fma.rn.f32x2 %0, %1, %2, %3;" : "=l"(r) : "l"(a), "l"(b), "l"(c));
    return r;
}
__device__ __forceinline__ unsigned cvt2(float lo, float hi) {   // -> f16x2
    unsigned r; asm("cvt.rn.f16x2.f32 %0, %1, %2;" : "=r"(r) : "f"(hi), "f"(lo));
    return r;
}
__device__ __forceinline__ unsigned tanh2(unsigned x) {
    unsigned r; asm("tanh.approx.f16x2 %0, %1;" : "=r"(r) : "r"(x)); return r;
}
__device__ __forceinline__ unsigned hfma2u(unsigned a, unsigned b, unsigned c) {
    unsigned r; asm("fma.rn.f16x2 %0, %1, %2, %3;" : "=r"(r) : "r"(a), "r"(b), "r"(c));
    return r;
}
// 4 halfs (uint2) -> float4
__device__ __forceinline__ float4 h4tof4(uint2 u) {
    float2 f0 = __half22float2(*(__half2*)&u.x);
    float2 f1 = __half22float2(*(__half2*)&u.y);
    return make_float4(f0.x, f0.y, f1.x, f1.y);
}

// Edge fill: count in-degree, push src into dst's bucket.
__global__ void k_fill(const int* __restrict__ ei) {
    int e = blockIdx.x * 256 + threadIdx.x;
    if (e >= NE) return;
    int s = __ldg(ei + e);
    int d = __ldg(ei + NE + e);
    int pos = atomicAdd(&g_cnt[d], 1);
    g_bkt[(size_t)d * CAP + pos] = (unsigned)s;
}

// Transpose + f16 convert: xT[n][b][24]. 2 quad-groups per thread.
// Element offset of quad i (= n*24 + b*6 + q) matches i directly.
__global__ void k_trans(const float* __restrict__ x) {
    int tid = blockIdx.x * 256 + threadIdx.x;
    if (tid >= TR_THREADS) return;
#pragma unroll
    for (int half = 0; half < 2; half++) {
        int i = tid + half * TR_THREADS;          // quad id in xT order
        int q = i % NQ;
        int b = (i / NQ) & 3;
        int n = i / (NQ * NB);
        float4 v = __ldg((const float4*)x + ((size_t)b * NN + n) * NQ + q);
        __half2 h0 = __floats2half2_rn(v.x, v.y);
        __half2 h1 = __floats2half2_rn(v.z, v.w);
        uint2 o;
        o.x = *(unsigned*)&h0; o.y = *(unsigned*)&h1;
        ((uint2*)g_xTh)[i] = o;
    }
}

// Fused weights + softmax. One block.
__global__ void k_wts(const float* __restrict__ att,
                      const float* __restrict__ czw, const float* __restrict__ czb,
                      const float* __restrict__ lzw, const float* __restrict__ lzb,
                      const float* __restrict__ chw, const float* __restrict__ chb,
                      const float* __restrict__ lhw, const float* __restrict__ lhb) {
    int lane = threadIdx.x & 31;
    int warp = threadIdx.x >> 5;
    if (threadIdx.x == 0) {
        float m = -1e30f;
        for (int i = 0; i < NT; i++) m = fmaxf(m, att[i]);
        float e[NT], s = 0.f;
        for (int i = 0; i < NT; i++) { e[i] = __expf(att[i] - m); s += e[i]; }
        float inv = 0.5f / s;                    // fold the 0.5 of (1-tz)/2 here
        for (int i = 0; i < NT; i++) g_p[i] = e[i] * inv;
    }
#pragma unroll
    for (int i = warp; i < 2 * NH; i += 8) {
        int gate = i >> 5;                       // 0 = z gate, 1 = h gate
        int h = i & 31;
        const float* cw = gate ? chw : czw;
        const float* cb = gate ? chb : czb;
        const float* lw = gate ? lhw : lzw;
        const float* lb = gate ? lhb : lzb;
        float w = lw[lane * NH + h];             // only first NH rows matter (H0=0)
        float m0 = cw[lane] * w;
        float m1 = cw[NH + lane] * w;
        float c  = cb[lane] * w;
#pragma unroll
        for (int off = 16; off; off >>= 1) {
            m0 += __shfl_xor_sync(0xffffffffu, m0, off);
            m1 += __shfl_xor_sync(0xffffffffu, m1, off);
            c  += __shfl_xor_sync(0xffffffffu, c, off);
        }
        if (lane == 0) {
            c += lb[h];
            if (gate == 0) {                     // negate: tanh(-az/2) = -tz
                g_Mz[h] = -0.5f * m0; g_Mz[NH + h] = -0.5f * m1; g_cz[h] = -0.5f * c;
            } else {
                g_Mh[h] = m0; g_Mh[NH + h] = m1; g_ch[h] = c;
            }
        }
    }
}

// Gather: one warp per node, all 4 batches. Fast path (cnt <= 32):
// norms pre-zeroed beyond cnt -> conditional-free 8-edge groups.
// Each lane loads 8B (uint2 of 4 halfs) per edge; accumulates in f32.
__global__ void __launch_bounds__(256)
k_gather() {
    int n    = blockIdx.x * 8 + (threadIdx.x >> 5);   // NN % 8 == 0
    int lane = threadIdx.x & 31;

    int   cnt  = g_cnt[n];
    float dinv = rsqrtf((float)(cnt + 1));            // deg = cnt + 1
    const unsigned* brow = g_bkt + (size_t)n * CAP;

    unsigned s0 = (lane < cnt) ? brow[lane] : 0u;     // coalesced 128B
    float   nm0 = (lane < cnt) ? dinv * rsqrtf((float)(g_cnt[s0] + 1)) : 0.f;

    bool act = lane < 24;
    const uint2* xTq = (const uint2*)g_xTh;

    float4 acc = make_float4(0.f, 0.f, 0.f, 0.f);
    if (act) {
        float4 xs = h4tof4(__ldg(xTq + (size_t)n * 24 + lane));
        float inv = dinv * dinv;                      // self-loop weight 1/deg
        acc.x = xs.x * inv; acc.y = xs.y * inv;
        acc.z = xs.z * inv; acc.w = xs.w * inv;
    }

    if (cnt <= 32) {
        int rc = (cnt + 7) >> 3;                      // 8-edge groups
        for (int g = 0; g < rc; g++) {
            int e = 8 * g;                            // e+i <= 31 for cnt<=32
            unsigned c_[8]; float n_[8];
#pragma unroll
            for (int i = 0; i < 8; i++) {
                c_[i] = __shfl_sync(0xffffffffu, s0, e + i);
                n_[i] = __shfl_sync(0xffffffffu, nm0, e + i);
            }
            if (act) {
                uint2 v[8];
#pragma unroll
                for (int i = 0; i < 8; i++)
                    v[i] = __ldg(xTq + (size_t)c_[i] * 24 + lane);
#pragma unroll
                for (int i = 0; i < 8; i++) {
                    float4 f = h4tof4(v[i]);
                    acc.x = fmaf(n_[i], f.x, acc.x);
                    acc.y = fmaf(n_[i], f.y, acc.y);
                    acc.z = fmaf(n_[i], f.z, acc.z);
                    acc.w = fmaf(n_[i], f.w, acc.w);
                }
            }
        }
    } else {
        // Generic fallback (in-degree > 32): lane-uniform per-edge loop.
        for (int e = 0; e < cnt; e++) {
            unsigned c = brow[e];
            float nm = dinv * rsqrtf((float)(g_cnt[c] + 1));
            if (act) {
                float4 f = h4tof4(__ldg(xTq + (size_t)c * 24 + lane));
                acc.x = fmaf(nm, f.x, acc.x); acc.y = fmaf(nm, f.y, acc.y);
                acc.z = fmaf(nm, f.z, acc.z); acc.w = fmaf(nm, f.w, acc.w);
            }
        }
    }
    if (act) {
        int q = lane % 6, b = lane / 6;
        ((float4*)g_y)[((size_t)b * NN + n) * NQ + q] = acc;
    }
}

// Pointwise collapse + head GEMV. One thread per (b, node).
// First blocks also re-zero g_cnt for the next graph replay.
__global__ void __launch_bounds__(256)
k_node(const float* __restrict__ hw, const float* __restrict__ hb,
       float* __restrict__ out) {
    __shared__ u64 s_Mz0[16], s_Mz1[16], s_czp[16];
    __shared__ u64 s_Mh0[16], s_Mh1[16], s_chp[16];
    __shared__ u64 s_hwp[NH * NO / 2];
    __shared__ u64 s_hbp[NO / 2];
    __shared__ unsigned s_ph[NT];
    int tid = threadIdx.x;
    int gid = blockIdx.x * 256 + tid;

    if (gid < NN) g_cnt[gid] = 0;                 // reset for next replay

    if (tid < 16) {
        s_Mz0[tid] = pk(g_Mz[2 * tid], g_Mz[2 * tid + 1]);
        s_Mz1[tid] = pk(g_Mz[NH + 2 * tid], g_Mz[NH + 2 * tid + 1]);
        s_czp[tid] = pk(g_cz[2 * tid], g_cz[2 * tid + 1]);
        s_Mh0[tid] = pk(g_Mh[2 * tid], g_Mh[2 * tid + 1]);
        s_Mh1[tid] = pk(g_Mh[NH + 2 * tid], g_Mh[NH + 2 * tid + 1]);
        s_chp[tid] = pk(g_ch[2 * tid], g_ch[2 * tid + 1]);
    }
    if (tid < NT) {
        __half2 h2 = __float2half2_rn(g_p[tid]);
        s_ph[tid] = *(unsigned*)&h2;
    }
    for (int i = tid; i < NH * NO / 2; i += 256) s_hwp[i] = ((const u64*)hw)[i];
    if (tid < NO / 2) s_hbp[tid] = ((const u64*)hb)[tid];
    __syncthreads();

    if (gid >= NB * NN) return;

    float yv[NODE_W];
    const float4* yp4 = (const float4*)(g_y + (size_t)gid * NODE_W);
#pragma unroll
    for (int i = 0; i < NQ; i++) {
        float4 v = yp4[i];
        yv[4 * i] = v.x; yv[4 * i + 1] = v.y; yv[4 * i + 2] = v.z; yv[4 * i + 3] = v.w;
    }
    u64 a2[NT], b2[NT];
#pragma unroll
    for (int t = 0; t < NT; t++) { a2[t] = pk(yv[t], yv[t]); b2[t] = pk(yv[NT + t], yv[NT + t]); }
    unsigned ph_[NT];
#pragma unroll
    for (int t = 0; t < NT; t++) ph_[t] = s_ph[t];

    u64 o2[NO / 2];
#pragma unroll
    for (int j = 0; j < NO / 2; j++) o2[j] = s_hbp[j];

#pragma unroll 1
    for (int k = 0; k < 16; k++) {                // h-pair index
        u64 mz0 = s_Mz0[k], mz1 = s_Mz1[k], czc = s_czp[k];
        u64 mh0 = s_Mh0[k], mh1 = s_Mh1[k], chc = s_chp[k];
        unsigned acc = 0;                         // half2 zero
#pragma unroll
        for (int t = 0; t < NT; t++) {
            u64 azn = fma2(a2[t], mz0, fma2(b2[t], mz1, czc));  // = -(az)/2 pair
            u64 ahp = fma2(a2[t], mh0, fma2(b2[t], mh1, chc));
            float zl, zh, hl, hh;
            upk(azn, zl, zh); upk(ahp, hl, hh);
            unsigned tzn = tanh2(cvt2(zl, zh));   // = -tz (odd fn, consts negated)
            unsigned th  = tanh2(cvt2(hl, hh));
            unsigned u   = hfma2u(tzn, th, th);   // (1 - tz) * th
            acc = hfma2u(ph_[t], u, acc);
        }
        __half2 ah2 = *(__half2*)&acc;
        float rl = fmaxf(__low2float(ah2), 0.f);  // relu, h = 2k
        float rh = fmaxf(__high2float(ah2), 0.f); // h = 2k+1
        u64 rl2 = pk(rl, rl), rh2 = pk(rh, rh);
        const u64* w0 = &s_hwp[(2 * k) * (NO / 2)];
        const u64* w1 = &s_hwp[(2 * k + 1) * (NO / 2)];
#pragma unroll
        for (int j = 0; j < NO / 2; j++)
            o2[j] = fma2(rl2, w0[j], fma2(rh2, w1[j], o2[j]));
    }

    float of[NO];
#pragma unroll
    for (int j = 0; j < NO / 2; j++) upk(o2[j], of[2 * j], of[2 * j + 1]);
    float4* op4 = (float4*)(out + (size_t)gid * NO);
#pragma unroll
    for (int j = 0; j < NO / 4; j++)
        op4[j] = make_float4(of[4 * j], of[4 * j + 1], of[4 * j + 2], of[4 * j + 3]);
}

extern "C" void kernel_launch(void* const* d_in, const int* in_sizes, int n_in,
                              void* d_out, int out_size) {
    const float* x   = (const float*)d_in[0];
    const int*   ei  = (const int*)d_in[1];
    const float* att = (const float*)d_in[2];
    const float* czw = (const float*)d_in[3];
    const float* czb = (const float*)d_in[4];
    const float* lzw = (const float*)d_in[5];
    const float* lzb = (const float*)d_in[6];
    // d_in[7..10] = conv_r_*, lin_r_* : dead (H0 == 0 -> H0*R == 0)
    const float* chw = (const float*)d_in[11];
    const float* chb = (const float*)d_in[12];
    const float* lhw = (const float*)d_in[13];
    const float* lhb = (const float*)d_in[14];
    const float* hw  = (const float*)d_in[15];
    const float* hb  = (const float*)d_in[16];
    float* out = (float*)d_out;

    // Host-side resources created once on the first (uncaptured correctness)
    // call. Device work per call is identical -> deterministic & capturable.
    static cudaStream_t sB = nullptr, sC = nullptr;
    static cudaEvent_t eF = nullptr, eB = nullptr, eC = nullptr;
    if (sB == nullptr) {
        cudaStreamCreateWithFlags(&sB, cudaStreamNonBlocking);
        cudaStreamCreateWithFlags(&sC, cudaStreamNonBlocking);
        cudaEventCreateWithFlags(&eF, cudaEventDisableTiming);
        cudaEventCreateWithFlags(&eB, cudaEventDisableTiming);
        cudaEventCreateWithFlags(&eC, cudaEventDisableTiming);
    }

    // Fork: bring side streams into the capture graph.
    cudaEventRecord(eF, 0);
    cudaStreamWaitEvent(sB, eF, 0);
    cudaStreamWaitEvent(sC, eF, 0);

    k_fill<<<FILL_BLOCKS, 256>>>(ei);                       // stream 0
    k_trans<<<TR_BLOCKS, 256, 0, sB>>>(x);                  // stream B
    k_wts<<<1, 256, 0, sC>>>(att, czw, czb, lzw, lzb,
                             chw, chb, lhw, lhb);           // stream C

    // Join B before gather (needs buckets + f16 xT).
    cudaEventRecord(eB, sB);
    cudaStreamWaitEvent(0, eB, 0);
    k_gather<<<NN / 8, 256>>>();

    // Join C before node (needs fused weights).
    cudaEventRecord(eC, sC);
    cudaStreamWaitEvent(0, eC, 0);
    k_node<<<(NB * NN + 255) / 256, 256>>>(hw, hb, out);
}

// round 13
// speedup vs baseline: 1.0917x; 1.0176x over previous
#include <cuda_runtime.h>
#include <cuda_fp16.h>

// ---------------------------------------------------------------------------
// Collapsed TemporalGNN (H0 == 0 in the scan; R gate dead):
//   y    = A_hat x           (pull-gather via per-dst buckets, no atomics)
//   Hn   = (1 + tanh(-(y@Mz + cz)/2)) * tanh(y@Mh + ch) * 0.5
//   acc  = sum_t p_t * Hn ;  out = relu(acc) @ head_w + head_b
// deg = cnt + 1 (self loops). Pipeline:
//   stream0: k_fillw (edge fill || fused weights) -> k_gather -> k_node
//   streamB: k_trans (x -> f16 xT[n][b][24]) --------^
// xT and y staged in f16; gather shuffles ONE packed (src|norm_f16) word per
// edge. Accumulation f32. g_cnt zero-init, re-zeroed by k_node each replay.
// ---------------------------------------------------------------------------

#define NB 4
#define NT 12
#define NN 30000
#define NH 32
#define NO 12
#define NE 240000
#define NODE_W 24               /* F_IN(2) * T(12) floats per (b,node) */
#define NQ (NODE_W / 4)
#define CAP 64
#define FILL_BLOCKS ((NE + 255) / 256)
#define TRQ (NB * NN * NQ)      /* 720000 quad-groups to transpose */
#define TR_THREADS (TRQ / 2)    /* 2 quads per thread */
#define TR_BLOCKS ((TR_THREADS + 255) / 256)

typedef unsigned long long u64;

__device__ int      g_cnt[NN];                    // zero-init; re-zeroed by k_node
__device__ unsigned g_bkt[(size_t)NN * CAP];      // src ids
__device__ __half   g_xTh[(size_t)NN * NB * NODE_W];  // f16 node-major x
__device__ __half   g_yh[(size_t)NB * NN * NODE_W];   // f16 aggregated y
__device__ float g_Mz[2 * NH];                    // NEGATED, x0.5
__device__ float g_Mh[2 * NH];
__device__ float g_cz[NH];                        // NEGATED, x0.5
__device__ float g_ch[NH];
__device__ float g_p[NT];                         // softmax * 0.5

// ---- packed-math helpers ----
__device__ __forceinline__ u64 pk(float lo, float hi) {
    u64 r; asm("mov.b64 %0, {%1, %2};" : "=l"(r) : "f"(lo), "f"(hi)); return r;
}
__device__ __forceinline__ void upk(u64 v, float& lo, float& hi) {
    asm("mov.b64 {%0, %1}, %2;" : "=f"(lo), "=f"(hi) : "l"(v));
}
__device__ __forceinline__ u64 fma2(u64 a, u64 b, u64 c) {
    u64 r; asm("fma.rn.f32x2 %0, %1, %2, %3;" : "=l"(r) : "l"(a), "l"(b), "l"(c));
    return r;
}
__device__ __forceinline__ unsigned cvt2(float lo, float hi) {   // -> f16x2
    unsigned r; asm("cvt.rn.f16x2.f32 %0, %1, %2;" : "=r"(r) : "f"(hi), "f"(lo));
    return r;
}
__device__ __forceinline__ unsigned tanh2(unsigned x) {
    unsigned r; asm("tanh.approx.f16x2 %0, %1;" : "=r"(r) : "r"(x)); return r;
}
__device__ __forceinline__ unsigned hfma2u(unsigned a, unsigned b, unsigned c) {
    unsigned r; asm("fma.rn.f16x2 %0, %1, %2, %3;" : "=r"(r) : "r"(a), "r"(b), "r"(c));
    return r;
}
// 4 halfs (uint2) -> float4
__device__ __forceinline__ float4 h4tof4(uint2 u) {
    float2 f0 = __half22float2(*(__half2*)&u.x);
    float2 f1 = __half22float2(*(__half2*)&u.y);
    return make_float4(f0.x, f0.y, f1.x, f1.y);
}

// Blocks [0, FILL_BLOCKS): edge fill. Block FILL_BLOCKS: weights + softmax.
__global__ void k_fillw(const int* __restrict__ ei,
                        const float* __restrict__ att,
                        const float* __restrict__ czw, const float* __restrict__ czb,
                        const float* __restrict__ lzw, const float* __restrict__ lzb,
                        const float* __restrict__ chw, const float* __restrict__ chb,
                        const float* __restrict__ lhw, const float* __restrict__ lhb) {
    if (blockIdx.x < FILL_BLOCKS) {
        int e = blockIdx.x * 256 + threadIdx.x;
        if (e >= NE) return;
        int s = __ldg(ei + e);
        int d = __ldg(ei + NE + e);
        int pos = atomicAdd(&g_cnt[d], 1);
        g_bkt[(size_t)d * CAP + pos] = (unsigned)s;
        return;
    }
    int lane = threadIdx.x & 31;
    int warp = threadIdx.x >> 5;
    if (threadIdx.x == 0) {
        float m = -1e30f;
        for (int i = 0; i < NT; i++) m = fmaxf(m, att[i]);
        float e[NT], s = 0.f;
        for (int i = 0; i < NT; i++) { e[i] = __expf(att[i] - m); s += e[i]; }
        float inv = 0.5f / s;                    // fold the 0.5 of (1-tz)/2 here
        for (int i = 0; i < NT; i++) g_p[i] = e[i] * inv;
    }
#pragma unroll
    for (int i = warp; i < 2 * NH; i += 8) {
        int gate = i >> 5;                       // 0 = z gate, 1 = h gate
        int h = i & 31;
        const float* cw = gate ? chw : czw;
        const float* cb = gate ? chb : czb;
        const float* lw = gate ? lhw : lzw;
        const float* lb = gate ? lhb : lzb;
        float w = lw[lane * NH + h];             // only first NH rows matter (H0=0)
        float m0 = cw[lane] * w;
        float m1 = cw[NH + lane] * w;
        float c  = cb[lane] * w;
#pragma unroll
        for (int off = 16; off; off >>= 1) {
            m0 += __shfl_xor_sync(0xffffffffu, m0, off);
            m1 += __shfl_xor_sync(0xffffffffu, m1, off);
            c  += __shfl_xor_sync(0xffffffffu, c, off);
        }
        if (lane == 0) {
            c += lb[h];
            if (gate == 0) {                     // negate: tanh(-az/2) = -tz
                g_Mz[h] = -0.5f * m0; g_Mz[NH + h] = -0.5f * m1; g_cz[h] = -0.5f * c;
            } else {
                g_Mh[h] = m0; g_Mh[NH + h] = m1; g_ch[h] = c;
            }
        }
    }
}

// Transpose + f16 convert: xT[n][b][24]. 2 quad-groups per thread.
__global__ void k_trans(const float* __restrict__ x) {
    int tid = blockIdx.x * 256 + threadIdx.x;
    if (tid >= TR_THREADS) return;
#pragma unroll
    for (int half = 0; half < 2; half++) {
        int i = tid + half * TR_THREADS;          // quad id in xT order
        int q = i % NQ;
        int b = (i / NQ) & 3;
        int n = i / (NQ * NB);
        float4 v = __ldg((const float4*)x + ((size_t)b * NN + n) * NQ + q);
        __half2 h0 = __floats2half2_rn(v.x, v.y);
        __half2 h1 = __floats2half2_rn(v.z, v.w);
        uint2 o;
        o.x = *(unsigned*)&h0; o.y = *(unsigned*)&h1;
        ((uint2*)g_xTh)[i] = o;
    }
}

// Gather: one warp per node, all 4 batches. One packed (src | norm_f16) word
// per edge -> ONE shuffle per edge. Norms pre-zeroed beyond cnt -> the 8-edge
// groups are conditional-free. f32 accumulation, f16 y store.
__global__ void __launch_bounds__(256)
k_gather() {
    int n    = blockIdx.x * 8 + (threadIdx.x >> 5);   // NN % 8 == 0
    int lane = threadIdx.x & 31;

    int   cnt  = g_cnt[n];
    float dinv = rsqrtf((float)(cnt + 1));            // deg = cnt + 1
    const unsigned* brow = g_bkt + (size_t)n * CAP;

    unsigned s0 = (lane < cnt) ? brow[lane] : 0u;     // coalesced 128B
    float   nm0 = (lane < cnt) ? dinv * rsqrtf((float)(g_cnt[s0] + 1)) : 0.f;
    // pack: src in low 16 (NN < 32768), f16 norm in high 16
    unsigned w0 = s0 | ((unsigned)__half_as_ushort(__float2half_rn(nm0)) << 16);

    bool act = lane < 24;
    const uint2* xTq = (const uint2*)g_xTh;

    float4 acc = make_float4(0.f, 0.f, 0.f, 0.f);
    if (act) {
        float4 xs = h4tof4(__ldg(xTq + (size_t)n * 24 + lane));
        float inv = dinv * dinv;                      // self-loop weight 1/deg
        acc.x = xs.x * inv; acc.y = xs.y * inv;
        acc.z = xs.z * inv; acc.w = xs.w * inv;
    }

    if (cnt <= 32) {
        int rc = (cnt + 7) >> 3;                      // 8-edge groups
        for (int g = 0; g < rc; g++) {
            int e = 8 * g;                            // e+i <= 31 for cnt<=32
            unsigned w_[8];
#pragma unroll
            for (int i = 0; i < 8; i++)
                w_[i] = __shfl_sync(0xffffffffu, w0, e + i);
            if (act) {
                uint2 v[8];
#pragma unroll
                for (int i = 0; i < 8; i++)
                    v[i] = __ldg(xTq + (size_t)(w_[i] & 0xFFFFu) * 24 + lane);
#pragma unroll
                for (int i = 0; i < 8; i++) {
                    float nm = __half2float(__ushort_as_half((unsigned short)(w_[i] >> 16)));
                    float4 f = h4tof4(v[i]);
                    acc.x = fmaf(nm, f.x, acc.x);
                    acc.y = fmaf(nm, f.y, acc.y);
                    acc.z = fmaf(nm, f.z, acc.z);
                    acc.w = fmaf(nm, f.w, acc.w);
                }
            }
        }
    } else {
        // Generic fallback (in-degree > 32): lane-uniform per-edge loop.
        for (int e = 0; e < cnt; e++) {
            unsigned c = brow[e];
            float nm = dinv * rsqrtf((float)(g_cnt[c] + 1));
            if (act) {
                float4 f = h4tof4(__ldg(xTq + (size_t)c * 24 + lane));
                acc.x = fmaf(nm, f.x, acc.x); acc.y = fmaf(nm, f.y, acc.y);
                acc.z = fmaf(nm, f.z, acc.z); acc.w = fmaf(nm, f.w, acc.w);
            }
        }
    }
    if (act) {
        int q = lane % 6, b = lane / 6;
        __half2 h0 = __floats2half2_rn(acc.x, acc.y);
        __half2 h1 = __floats2half2_rn(acc.z, acc.w);
        uint2 o; o.x = *(unsigned*)&h0; o.y = *(unsigned*)&h1;
        ((uint2*)g_yh)[((size_t)b * NN + n) * NQ + q] = o;
    }
}

// Pointwise collapse + head GEMV. One thread per (b, node); y read as f16
// (48B/thread). First blocks also re-zero g_cnt for the next graph replay.
__global__ void __launch_bounds__(256)
k_node(const float* __restrict__ hw, const float* __restrict__ hb,
       float* __restrict__ out) {
    __shared__ u64 s_Mz0[16], s_Mz1[16], s_czp[16];
    __shared__ u64 s_Mh0[16], s_Mh1[16], s_chp[16];
    __shared__ u64 s_hwp[NH * NO / 2];
    __shared__ u64 s_hbp[NO / 2];
    __shared__ unsigned s_ph[NT];
    int tid = threadIdx.x;
    int gid = blockIdx.x * 256 + tid;

    if (gid < NN) g_cnt[gid] = 0;                 // reset for next replay

    if (tid < 16) {
        s_Mz0[tid] = pk(g_Mz[2 * tid], g_Mz[2 * tid + 1]);
        s_Mz1[tid] = pk(g_Mz[NH + 2 * tid], g_Mz[NH + 2 * tid + 1]);
        s_czp[tid] = pk(g_cz[2 * tid], g_cz[2 * tid + 1]);
        s_Mh0[tid] = pk(g_Mh[2 * tid], g_Mh[2 * tid + 1]);
        s_Mh1[tid] = pk(g_Mh[NH + 2 * tid], g_Mh[NH + 2 * tid + 1]);
        s_chp[tid] = pk(g_ch[2 * tid], g_ch[2 * tid + 1]);
    }
    if (tid < NT) {
        __half2 h2 = __float2half2_rn(g_p[tid]);
        s_ph[tid] = *(unsigned*)&h2;
    }
    for (int i = tid; i < NH * NO / 2; i += 256) s_hwp[i] = ((const u64*)hw)[i];
    if (tid < NO / 2) s_hbp[tid] = ((const u64*)hb)[tid];
    __syncthreads();

    if (gid >= NB * NN) return;

    // y row: 24 halfs = 48B = 3 x uint4 (16B-aligned: 48 * gid is 16-aligned)
    float yv[NODE_W];
    const uint4* yq = (const uint4*)g_yh + (size_t)gid * 3;
#pragma unroll
    for (int i = 0; i < 3; i++) {
        uint4 u = __ldg(yq + i);
        float2 f0 = __half22float2(*(__half2*)&u.x);
        float2 f1 = __half22float2(*(__half2*)&u.y);
        float2 f2 = __half22float2(*(__half2*)&u.z);
        float2 f3 = __half22float2(*(__half2*)&u.w);
        yv[8 * i + 0] = f0.x; yv[8 * i + 1] = f0.y;
        yv[8 * i + 2] = f1.x; yv[8 * i + 3] = f1.y;
        yv[8 * i + 4] = f2.x; yv[8 * i + 5] = f2.y;
        yv[8 * i + 6] = f3.x; yv[8 * i + 7] = f3.y;
    }
    u64 a2[NT], b2[NT];
#pragma unroll
    for (int t = 0; t < NT; t++) { a2[t] = pk(yv[t], yv[t]); b2[t] = pk(yv[NT + t], yv[NT + t]); }
    unsigned ph_[NT];
#pragma unroll
    for (int t = 0; t < NT; t++) ph_[t] = s_ph[t];

    u64 o2[NO / 2];
#pragma unroll
    for (int j = 0; j < NO / 2; j++) o2[j] = s_hbp[j];

#pragma unroll 1
    for (int k = 0; k < 16; k++) {                // h-pair index
        u64 mz0 = s_Mz0[k], mz1 = s_Mz1[k], czc = s_czp[k];
        u64 mh0 = s_Mh0[k], mh1 = s_Mh1[k], chc = s_chp[k];
        unsigned acc = 0;                         // half2 zero
#pragma unroll
        for (int t = 0; t < NT; t++) {
            u64 azn = fma2(a2[t], mz0, fma2(b2[t], mz1, czc));  // = -(az)/2 pair
            u64 ahp = fma2(a2[t], mh0, fma2(b2[t], mh1, chc));
            float zl, zh, hl, hh;
            upk(azn, zl, zh); upk(ahp, hl, hh);
            unsigned tzn = tanh2(cvt2(zl, zh));   // = -tz (odd fn, consts negated)
            unsigned th  = tanh2(cvt2(hl, hh));
            unsigned u   = hfma2u(tzn, th, th);   // (1 - tz) * th
            acc = hfma2u(ph_[t], u, acc);
        }
        __half2 ah2 = *(__half2*)&acc;
        float rl = fmaxf(__low2float(ah2), 0.f);  // relu, h = 2k
        float rh = fmaxf(__high2float(ah2), 0.f); // h = 2k+1
        u64 rl2 = pk(rl, rl), rh2 = pk(rh, rh);
        const u64* w0 = &s_hwp[(2 * k) * (NO / 2)];
        const u64* w1 = &s_hwp[(2 * k + 1) * (NO / 2)];
#pragma unroll
        for (int j = 0; j < NO / 2; j++)
            o2[j] = fma2(rl2, w0[j], fma2(rh2, w1[j], o2[j]));
    }

    float of[NO];
#pragma unroll
    for (int j = 0; j < NO / 2; j++) upk(o2[j], of[2 * j], of[2 * j + 1]);
    float4* op4 = (float4*)(out + (size_t)gid * NO);
#pragma unroll
    for (int j = 0; j < NO / 4; j++)
        op4[j] = make_float4(of[4 * j], of[4 * j + 1], of[4 * j + 2], of[4 * j + 3]);
}

extern "C" void kernel_launch(void* const* d_in, const int* in_sizes, int n_in,
                              void* d_out, int out_size) {
    const float* x   = (const float*)d_in[0];
    const int*   ei  = (const int*)d_in[1];
    const float* att = (const float*)d_in[2];
    const float* czw = (const float*)d_in[3];
    const float* czb = (const float*)d_in[4];
    const float* lzw = (const float*)d_in[5];
    const float* lzb = (const float*)d_in[6];
    // d_in[7..10] = conv_r_*, lin_r_* : dead (H0 == 0 -> H0*R == 0)
    const float* chw = (const float*)d_in[11];
    const float* chb = (const float*)d_in[12];
    const float* lhw = (const float*)d_in[13];
    const float* lhb = (const float*)d_in[14];
    const float* hw  = (const float*)d_in[15];
    const float* hb  = (const float*)d_in[16];
    float* out = (float*)d_out;

    // Host-side resources created once on the first (uncaptured correctness)
    // call. Device work per call is identical -> deterministic & capturable.
    static cudaStream_t sB = nullptr;
    static cudaEvent_t eF = nullptr, eB = nullptr;
    if (sB == nullptr) {
        cudaStreamCreateWithFlags(&sB, cudaStreamNonBlocking);
        cudaEventCreateWithFlags(&eF, cudaEventDisableTiming);
        cudaEventCreateWithFlags(&eB, cudaEventDisableTiming);
    }

    // Fork: bring the transpose stream into the capture graph.
    cudaEventRecord(eF, 0);
    cudaStreamWaitEvent(sB, eF, 0);

    k_fillw<<<FILL_BLOCKS + 1, 256>>>(ei, att, czw, czb, lzw, lzb,
                                      chw, chb, lhw, lhb);  // stream 0
    k_trans<<<TR_BLOCKS, 256, 0, sB>>>(x);                  // stream B

    // Join B before gather (needs buckets + f16 xT).
    cudaEventRecord(eB, sB);
    cudaStreamWaitEvent(0, eB, 0);
    k_gather<<<NN / 8, 256>>>();

    k_node<<<(NB * NN + 255) / 256, 256>>>(hw, hb, out);
}

// round 14
// speedup vs baseline: 1.1007x; 1.0083x over previous
#include <cuda_runtime.h>
#include <cuda_fp16.h>

// ---------------------------------------------------------------------------
// Collapsed TemporalGNN (H0 == 0 in the scan; R gate dead):
//   y    = A_hat x           (pull-gather via per-dst buckets, no atomics)
//   Hn   = (1 + tanh(-(y@Mz + cz)/2)) * tanh(y@Mh + ch) * 0.5
//   acc  = sum_t p_t * Hn ;  out = relu(acc) @ head_w + head_b
// deg = cnt + 1 (self loops). Pipeline:
//   stream0: k_fillw (edge fill || fused weights) -> k_gather -> k_node
//   streamB: k_trans (x -> f16 xT[n][b][24]) --------^
// xT/y staged f16. k_node gate path is PURE f16x2 (6 HFMA2 + 2 tanh2 per
// (t,h-pair); no cvt/pack in the loop); head GEMV stays f32x2.
// g_cnt zero-init, re-zeroed by k_node each replay.
// ---------------------------------------------------------------------------

#define NB 4
#define NT 12
#define NN 30000
#define NH 32
#define NO 12
#define NE 240000
#define NODE_W 24               /* F_IN(2) * T(12) floats per (b,node) */
#define NQ (NODE_W / 4)
#define CAP 64
#define FILL_BLOCKS ((NE + 255) / 256)
#define TRQ (NB * NN * NQ)      /* 720000 quad-groups to transpose */
#define TR_THREADS (TRQ / 2)    /* 2 quads per thread */
#define TR_BLOCKS ((TR_THREADS + 255) / 256)

typedef unsigned long long u64;

__device__ int      g_cnt[NN];                    // zero-init; re-zeroed by k_node
__device__ unsigned g_bkt[(size_t)NN * CAP];      // src ids
__device__ __half   g_xTh[(size_t)NN * NB * NODE_W];  // f16 node-major x
__device__ __half   g_yh[(size_t)NB * NN * NODE_W];   // f16 aggregated y
__device__ float g_Mz[2 * NH];                    // NEGATED, x0.5
__device__ float g_Mh[2 * NH];
__device__ float g_cz[NH];                        // NEGATED, x0.5
__device__ float g_ch[NH];
__device__ float g_p[NT];                         // softmax * 0.5

// ---- packed-math helpers ----
__device__ __forceinline__ u64 pk(float lo, float hi) {
    u64 r; asm("mov.b64 %0, {%1, %2};" : "=l"(r) : "f"(lo), "f"(hi)); return r;
}
__device__ __forceinline__ void upk(u64 v, float& lo, float& hi) {
    asm("mov.b64 {%0, %1}, %2;" : "=f"(lo), "=f"(hi) : "l"(v));
}
__device__ __forceinline__ u64 fma2(u64 a, u64 b, u64 c) {
    u64 r; asm("fma.rn.f32x2 %0, %1, %2, %3;" : "=l"(r) : "l"(a), "l"(b), "l"(c));
    return r;
}
__device__ __forceinline__ unsigned tanh2(unsigned x) {
    unsigned r; asm("tanh.approx.f16x2 %0, %1;" : "=r"(r) : "r"(x)); return r;
}
__device__ __forceinline__ unsigned hfma2u(unsigned a, unsigned b, unsigned c) {
    unsigned r; asm("fma.rn.f16x2 %0, %1, %2, %3;" : "=r"(r) : "r"(a), "r"(b), "r"(c));
    return r;
}
// 4 halfs (uint2) -> float4
__device__ __forceinline__ float4 h4tof4(uint2 u) {
    float2 f0 = __half22float2(*(__half2*)&u.x);
    float2 f1 = __half22float2(*(__half2*)&u.y);
    return make_float4(f0.x, f0.y, f1.x, f1.y);
}
__device__ __forceinline__ unsigned h2u(__half2 h) { return *(unsigned*)&h; }

// Blocks [0, FILL_BLOCKS): edge fill. Block FILL_BLOCKS: weights + softmax.
__global__ void k_fillw(const int* __restrict__ ei,
                        const float* __restrict__ att,
                        const float* __restrict__ czw, const float* __restrict__ czb,
                        const float* __restrict__ lzw, const float* __restrict__ lzb,
                        const float* __restrict__ chw, const float* __restrict__ chb,
                        const float* __restrict__ lhw, const float* __restrict__ lhb) {
    if (blockIdx.x < FILL_BLOCKS) {
        int e = blockIdx.x * 256 + threadIdx.x;
        if (e >= NE) return;
        int s = __ldg(ei + e);
        int d = __ldg(ei + NE + e);
        int pos = atomicAdd(&g_cnt[d], 1);
        g_bkt[(size_t)d * CAP + pos] = (unsigned)s;
        return;
    }
    int lane = threadIdx.x & 31;
    int warp = threadIdx.x >> 5;
    if (threadIdx.x == 0) {
        float m = -1e30f;
        for (int i = 0; i < NT; i++) m = fmaxf(m, att[i]);
        float e[NT], s = 0.f;
        for (int i = 0; i < NT; i++) { e[i] = __expf(att[i] - m); s += e[i]; }
        float inv = 0.5f / s;                    // fold the 0.5 of (1-tz)/2 here
        for (int i = 0; i < NT; i++) g_p[i] = e[i] * inv;
    }
#pragma unroll
    for (int i = warp; i < 2 * NH; i += 8) {
        int gate = i >> 5;                       // 0 = z gate, 1 = h gate
        int h = i & 31;
        const float* cw = gate ? chw : czw;
        const float* cb = gate ? chb : czb;
        const float* lw = gate ? lhw : lzw;
        const float* lb = gate ? lhb : lzb;
        float w = lw[lane * NH + h];             // only first NH rows matter (H0=0)
        float m0 = cw[lane] * w;
        float m1 = cw[NH + lane] * w;
        float c  = cb[lane] * w;
#pragma unroll
        for (int off = 16; off; off >>= 1) {
            m0 += __shfl_xor_sync(0xffffffffu, m0, off);
            m1 += __shfl_xor_sync(0xffffffffu, m1, off);
            c  += __shfl_xor_sync(0xffffffffu, c, off);
        }
        if (lane == 0) {
            c += lb[h];
            if (gate == 0) {                     // negate: tanh(-az/2) = -tz
                g_Mz[h] = -0.5f * m0; g_Mz[NH + h] = -0.5f * m1; g_cz[h] = -0.5f * c;
            } else {
                g_Mh[h] = m0; g_Mh[NH + h] = m1; g_ch[h] = c;
            }
        }
    }
}

// Transpose + f16 convert: xT[n][b][24]. 2 quad-groups per thread.
__global__ void k_trans(const float* __restrict__ x) {
    int tid = blockIdx.x * 256 + threadIdx.x;
    if (tid >= TR_THREADS) return;
#pragma unroll
    for (int half = 0; half < 2; half++) {
        int i = tid + half * TR_THREADS;          // quad id in xT order
        int q = i % NQ;
        int b = (i / NQ) & 3;
        int n = i / (NQ * NB);
        float4 v = __ldg((const float4*)x + ((size_t)b * NN + n) * NQ + q);
        __half2 h0 = __floats2half2_rn(v.x, v.y);
        __half2 h1 = __floats2half2_rn(v.z, v.w);
        uint2 o;
        o.x = *(unsigned*)&h0; o.y = *(unsigned*)&h1;
        ((uint2*)g_xTh)[i] = o;
    }
}

// Gather: one warp per node, all 4 batches. One packed (src | norm_f16) word
// per edge -> ONE shuffle per edge. Norms pre-zeroed beyond cnt -> the 8-edge
// groups are conditional-free. f32 accumulation, f16 y store.
__global__ void __launch_bounds__(256)
k_gather() {
    int n    = blockIdx.x * 8 + (threadIdx.x >> 5);   // NN % 8 == 0
    int lane = threadIdx.x & 31;

    int   cnt  = g_cnt[n];
    float dinv = rsqrtf((float)(cnt + 1));            // deg = cnt + 1
    const unsigned* brow = g_bkt + (size_t)n * CAP;

    unsigned s0 = (lane < cnt) ? brow[lane] : 0u;     // coalesced 128B
    float   nm0 = (lane < cnt) ? dinv * rsqrtf((float)(g_cnt[s0] + 1)) : 0.f;
    // pack: src in low 16 (NN < 32768), f16 norm in high 16
    unsigned w0 = s0 | ((unsigned)__half_as_ushort(__float2half_rn(nm0)) << 16);

    bool act = lane < 24;
    const uint2* xTq = (const uint2*)g_xTh;

    float4 acc = make_float4(0.f, 0.f, 0.f, 0.f);
    if (act) {
        float4 xs = h4tof4(__ldg(xTq + (size_t)n * 24 + lane));
        float inv = dinv * dinv;                      // self-loop weight 1/deg
        acc.x = xs.x * inv; acc.y = xs.y * inv;
        acc.z = xs.z * inv; acc.w = xs.w * inv;
    }

    if (cnt <= 32) {
        int rc = (cnt + 7) >> 3;                      // 8-edge groups
        for (int g = 0; g < rc; g++) {
            int e = 8 * g;                            // e+i <= 31 for cnt<=32
            unsigned w_[8];
#pragma unroll
            for (int i = 0; i < 8; i++)
                w_[i] = __shfl_sync(0xffffffffu, w0, e + i);
            if (act) {
                uint2 v[8];
#pragma unroll
                for (int i = 0; i < 8; i++)
                    v[i] = __ldg(xTq + (size_t)(w_[i] & 0xFFFFu) * 24 + lane);
#pragma unroll
                for (int i = 0; i < 8; i++) {
                    float nm = __half2float(__ushort_as_half((unsigned short)(w_[i] >> 16)));
                    float4 f = h4tof4(v[i]);
                    acc.x = fmaf(nm, f.x, acc.x);
                    acc.y = fmaf(nm, f.y, acc.y);
                    acc.z = fmaf(nm, f.z, acc.z);
                    acc.w = fmaf(nm, f.w, acc.w);
                }
            }
        }
    } else {
        // Generic fallback (in-degree > 32): lane-uniform per-edge loop.
        for (int e = 0; e < cnt; e++) {
            unsigned c = brow[e];
            float nm = dinv * rsqrtf((float)(g_cnt[c] + 1));
            if (act) {
                float4 f = h4tof4(__ldg(xTq + (size_t)c * 24 + lane));
                acc.x = fmaf(nm, f.x, acc.x); acc.y = fmaf(nm, f.y, acc.y);
                acc.z = fmaf(nm, f.z, acc.z); acc.w = fmaf(nm, f.w, acc.w);
            }
        }
    }
    if (act) {
        int q = lane % 6, b = lane / 6;
        __half2 h0 = __floats2half2_rn(acc.x, acc.y);
        __half2 h1 = __floats2half2_rn(acc.z, acc.w);
        uint2 o; o.x = *(unsigned*)&h0; o.y = *(unsigned*)&h1;
        ((uint2*)g_yh)[((size_t)b * NN + n) * NQ + q] = o;
    }
}

// Pointwise collapse + head GEMV. One thread per (b, node).
// Gate path pure f16x2: per (t, h-pair) exactly 6 HFMA2 + 2 tanh2.
// Head GEMV in f32x2. First blocks re-zero g_cnt for the next replay.
__global__ void __launch_bounds__(256)
k_node(const float* __restrict__ hw, const float* __restrict__ hb,
       float* __restrict__ out) {
    __shared__ unsigned s_Mz0[16], s_Mz1[16], s_czp[16];   // half2 per h-pair
    __shared__ unsigned s_Mh0[16], s_Mh1[16], s_chp[16];
    __shared__ u64 s_hwp[NH * NO / 2];
    __shared__ u64 s_hbp[NO / 2];
    __shared__ unsigned s_ph[NT];
    int tid = threadIdx.x;
    int gid = blockIdx.x * 256 + tid;

    if (gid < NN) g_cnt[gid] = 0;                 // reset for next replay

    if (tid < 16) {
        s_Mz0[tid] = h2u(__floats2half2_rn(g_Mz[2 * tid], g_Mz[2 * tid + 1]));
        s_Mz1[tid] = h2u(__floats2half2_rn(g_Mz[NH + 2 * tid], g_Mz[NH + 2 * tid + 1]));
        s_czp[tid] = h2u(__floats2half2_rn(g_cz[2 * tid], g_cz[2 * tid + 1]));
        s_Mh0[tid] = h2u(__floats2half2_rn(g_Mh[2 * tid], g_Mh[2 * tid + 1]));
        s_Mh1[tid] = h2u(__floats2half2_rn(g_Mh[NH + 2 * tid], g_Mh[NH + 2 * tid + 1]));
        s_chp[tid] = h2u(__floats2half2_rn(g_ch[2 * tid], g_ch[2 * tid + 1]));
    }
    if (tid < NT) s_ph[tid] = h2u(__float2half2_rn(g_p[tid]));
    for (int i = tid; i < NH * NO / 2; i += 256) s_hwp[i] = ((const u64*)hw)[i];
    if (tid < NO / 2) s_hbp[tid] = ((const u64*)hb)[tid];
    __syncthreads();

    if (gid >= NB * NN) return;

    // y row: 24 halfs = 48B = 3 x uint4. Broadcast each half -> half2.
    __half yh[NODE_W];
    const uint4* yq = (const uint4*)g_yh + (size_t)gid * 3;
#pragma unroll
    for (int i = 0; i < 3; i++) {
        uint4 u = __ldg(yq + i);
        *(uint4*)(yh + 8 * i) = u;
    }
    unsigned a2[NT], b2[NT];
#pragma unroll
    for (int t = 0; t < NT; t++) {
        a2[t] = h2u(__half2half2(yh[t]));
        b2[t] = h2u(__half2half2(yh[NT + t]));
    }
    unsigned ph_[NT];
#pragma unroll
    for (int t = 0; t < NT; t++) ph_[t] = s_ph[t];

    u64 o2[NO / 2];
#pragma unroll
    for (int j = 0; j < NO / 2; j++) o2[j] = s_hbp[j];

#pragma unroll 1
    for (int k = 0; k < 16; k++) {                // h-pair index
        unsigned mz0 = s_Mz0[k], mz1 = s_Mz1[k], czc = s_czp[k];
        unsigned mh0 = s_Mh0[k], mh1 = s_Mh1[k], chc = s_chp[k];
        unsigned acc = 0;                         // half2 zero
#pragma unroll
        for (int t = 0; t < NT; t++) {
            unsigned azn = hfma2u(a2[t], mz0, hfma2u(b2[t], mz1, czc)); // -(az)/2
            unsigned ahp = hfma2u(a2[t], mh0, hfma2u(b2[t], mh1, chc));
            unsigned tzn = tanh2(azn);            // = -tz (odd fn, consts negated)
            unsigned th  = tanh2(ahp);
            unsigned u   = hfma2u(tzn, th, th);   // (1 - tz) * th
            acc = hfma2u(ph_[t], u, acc);
        }
        __half2 ah2 = *(__half2*)&acc;
        float rl = fmaxf(__low2float(ah2), 0.f);  // relu, h = 2k
        float rh = fmaxf(__high2float(ah2), 0.f); // h = 2k+1
        u64 rl2 = pk(rl, rl), rh2 = pk(rh, rh);
        const u64* w0 = &s_hwp[(2 * k) * (NO / 2)];
        const u64* w1 = &s_hwp[(2 * k + 1) * (NO / 2)];
#pragma unroll
        for (int j = 0; j < NO / 2; j++)
            o2[j] = fma2(rl2, w0[j], fma2(rh2, w1[j], o2[j]));
    }

    float of[NO];
#pragma unroll
    for (int j = 0; j < NO / 2; j++) upk(o2[j], of[2 * j], of[2 * j + 1]);
    float4* op4 = (float4*)(out + (size_t)gid * NO);
#pragma unroll
    for (int j = 0; j < NO / 4; j++)
        op4[j] = make_float4(of[4 * j], of[4 * j + 1], of[4 * j + 2], of[4 * j + 3]);
}

extern "C" void kernel_launch(void* const* d_in, const int* in_sizes, int n_in,
                              void* d_out, int out_size) {
    const float* x   = (const float*)d_in[0];
    const int*   ei  = (const int*)d_in[1];
    const float* att = (const float*)d_in[2];
    const float* czw = (const float*)d_in[3];
    const float* czb = (const float*)d_in[4];
    const float* lzw = (const float*)d_in[5];
    const float* lzb = (const float*)d_in[6];
    // d_in[7..10] = conv_r_*, lin_r_* : dead (H0 == 0 -> H0*R == 0)
    const float* chw = (const float*)d_in[11];
    const float* chb = (const float*)d_in[12];
    const float* lhw = (const float*)d_in[13];
    const float* lhb = (const float*)d_in[14];
    const float* hw  = (const float*)d_in[15];
    const float* hb  = (const float*)d_in[16];
    float* out = (float*)d_out;

    // Host-side resources created once on the first (uncaptured correctness)
    // call. Device work per call is identical -> deterministic & capturable.
    static cudaStream_t sB = nullptr;
    static cudaEvent_t eF = nullptr, eB = nullptr;
    if (sB == nullptr) {
        cudaStreamCreateWithFlags(&sB, cudaStreamNonBlocking);
        cudaEventCreateWithFlags(&eF, cudaEventDisableTiming);
        cudaEventCreateWithFlags(&eB, cudaEventDisableTiming);
    }

    // Fork: bring the transpose stream into the capture graph.
    cudaEventRecord(eF, 0);
    cudaStreamWaitEvent(sB, eF, 0);

    k_fillw<<<FILL_BLOCKS + 1, 256>>>(ei, att, czw, czb, lzw, lzb,
                                      chw, chb, lhw, lhb);  // stream 0
    k_trans<<<TR_BLOCKS, 256, 0, sB>>>(x);                  // stream B

    // Join B before gather (needs buckets + f16 xT).
    cudaEventRecord(eB, sB);
    cudaStreamWaitEvent(0, eB, 0);
    k_gather<<<NN / 8, 256>>>();

    k_node<<<(NB * NN + 255) / 256, 256>>>(hw, hb, out);
}

// round 15
// speedup vs baseline: 1.1979x; 1.0883x over previous
#include <cuda_runtime.h>
#include <cuda_fp16.h>

// ---------------------------------------------------------------------------
// Collapsed TemporalGNN (H0 == 0 in the scan; R gate dead):
//   y    = A_hat x           (pull-gather via per-dst buckets, no atomics)
//   Hn   = (1 + tanh(-(y@Mz + cz)/2)) * tanh(y@Mh + ch) * 0.5
//   acc  = sum_t p_t * Hn ;  out = relu(acc) @ head_w + head_b
// deg = cnt + 1 (self loops). Pipeline:
//   stream0: k_fillw (edge fill || fused weights) -> k_gather -> k_node
//   streamB: k_trans (x -> f16 xT[n][b][24]) --------^
// xT/y staged f16. k_node: TWO threads per (b,node), 8 h-pairs each (pure
// f16x2 gate math), partial head GEMV exchanged via shfl_xor(1).
// g_cnt zero-init, re-zeroed by k_node each replay.
// ---------------------------------------------------------------------------

#define NB 4
#define NT 12
#define NN 30000
#define NH 32
#define NO 12
#define NE 240000
#define NODE_W 24               /* F_IN(2) * T(12) floats per (b,node) */
#define NQ (NODE_W / 4)
#define CAP 64
#define FILL_BLOCKS ((NE + 255) / 256)
#define TRQ (NB * NN * NQ)      /* 720000 quad-groups to transpose */
#define TR_THREADS (TRQ / 2)    /* 2 quads per thread */
#define TR_BLOCKS ((TR_THREADS + 255) / 256)
#define NODE_THREADS (NB * NN * 2)   /* 2 threads per (b,node) */

typedef unsigned long long u64;

__device__ int      g_cnt[NN];                    // zero-init; re-zeroed by k_node
__device__ unsigned g_bkt[(size_t)NN * CAP];      // src ids
__device__ __half   g_xTh[(size_t)NN * NB * NODE_W];  // f16 node-major x
__device__ __half   g_yh[(size_t)NB * NN * NODE_W];   // f16 aggregated y
__device__ float g_Mz[2 * NH];                    // NEGATED, x0.5
__device__ float g_Mh[2 * NH];
__device__ float g_cz[NH];                        // NEGATED, x0.5
__device__ float g_ch[NH];
__device__ float g_p[NT];                         // softmax * 0.5

// ---- packed-math helpers ----
__device__ __forceinline__ u64 pk(float lo, float hi) {
    u64 r; asm("mov.b64 %0, {%1, %2};" : "=l"(r) : "f"(lo), "f"(hi)); return r;
}
__device__ __forceinline__ void upk(u64 v, float& lo, float& hi) {
    asm("mov.b64 {%0, %1}, %2;" : "=f"(lo), "=f"(hi) : "l"(v));
}
__device__ __forceinline__ u64 fma2(u64 a, u64 b, u64 c) {
    u64 r; asm("fma.rn.f32x2 %0, %1, %2, %3;" : "=l"(r) : "l"(a), "l"(b), "l"(c));
    return r;
}
__device__ __forceinline__ u64 add2(u64 a, u64 b) {
    u64 r; asm("add.rn.f32x2 %0, %1, %2;" : "=l"(r) : "l"(a), "l"(b)); return r;
}
__device__ __forceinline__ unsigned tanh2(unsigned x) {
    unsigned r; asm("tanh.approx.f16x2 %0, %1;" : "=r"(r) : "r"(x)); return r;
}
__device__ __forceinline__ unsigned hfma2u(unsigned a, unsigned b, unsigned c) {
    unsigned r; asm("fma.rn.f16x2 %0, %1, %2, %3;" : "=r"(r) : "r"(a), "r"(b), "r"(c));
    return r;
}
// 4 halfs (uint2) -> float4
__device__ __forceinline__ float4 h4tof4(uint2 u) {
    float2 f0 = __half22float2(*(__half2*)&u.x);
    float2 f1 = __half22float2(*(__half2*)&u.y);
    return make_float4(f0.x, f0.y, f1.x, f1.y);
}
__device__ __forceinline__ unsigned h2u(__half2 h) { return *(unsigned*)&h; }

// Blocks [0, FILL_BLOCKS): edge fill. Block FILL_BLOCKS: weights + softmax.
__global__ void k_fillw(const int* __restrict__ ei,
                        const float* __restrict__ att,
                        const float* __restrict__ czw, const float* __restrict__ czb,
                        const float* __restrict__ lzw, const float* __restrict__ lzb,
                        const float* __restrict__ chw, const float* __restrict__ chb,
                        const float* __restrict__ lhw, const float* __restrict__ lhb) {
    if (blockIdx.x < FILL_BLOCKS) {
        int e = blockIdx.x * 256 + threadIdx.x;
        if (e >= NE) return;
        int s = __ldg(ei + e);
        int d = __ldg(ei + NE + e);
        int pos = atomicAdd(&g_cnt[d], 1);
        g_bkt[(size_t)d * CAP + pos] = (unsigned)s;
        return;
    }
    int lane = threadIdx.x & 31;
    int warp = threadIdx.x >> 5;
    if (threadIdx.x == 0) {
        float m = -1e30f;
        for (int i = 0; i < NT; i++) m = fmaxf(m, att[i]);
        float e[NT], s = 0.f;
        for (int i = 0; i < NT; i++) { e[i] = __expf(att[i] - m); s += e[i]; }
        float inv = 0.5f / s;                    // fold the 0.5 of (1-tz)/2 here
        for (int i = 0; i < NT; i++) g_p[i] = e[i] * inv;
    }
#pragma unroll
    for (int i = warp; i < 2 * NH; i += 8) {
        int gate = i >> 5;                       // 0 = z gate, 1 = h gate
        int h = i & 31;
        const float* cw = gate ? chw : czw;
        const float* cb = gate ? chb : czb;
        const float* lw = gate ? lhw : lzw;
        const float* lb = gate ? lhb : lzb;
        float w = lw[lane * NH + h];             // only first NH rows matter (H0=0)
        float m0 = cw[lane] * w;
        float m1 = cw[NH + lane] * w;
        float c  = cb[lane] * w;
#pragma unroll
        for (int off = 16; off; off >>= 1) {
            m0 += __shfl_xor_sync(0xffffffffu, m0, off);
            m1 += __shfl_xor_sync(0xffffffffu, m1, off);
            c  += __shfl_xor_sync(0xffffffffu, c, off);
        }
        if (lane == 0) {
            c += lb[h];
            if (gate == 0) {                     // negate: tanh(-az/2) = -tz
                g_Mz[h] = -0.5f * m0; g_Mz[NH + h] = -0.5f * m1; g_cz[h] = -0.5f * c;
            } else {
                g_Mh[h] = m0; g_Mh[NH + h] = m1; g_ch[h] = c;
            }
        }
    }
}

// Transpose + f16 convert: xT[n][b][24]. 2 quad-groups per thread.
__global__ void k_trans(const float* __restrict__ x) {
    int tid = blockIdx.x * 256 + threadIdx.x;
    if (tid >= TR_THREADS) return;
#pragma unroll
    for (int half = 0; half < 2; half++) {
        int i = tid + half * TR_THREADS;          // quad id in xT order
        int q = i % NQ;
        int b = (i / NQ) & 3;
        int n = i / (NQ * NB);
        float4 v = __ldg((const float4*)x + ((size_t)b * NN + n) * NQ + q);
        __half2 h0 = __floats2half2_rn(v.x, v.y);
        __half2 h1 = __floats2half2_rn(v.z, v.w);
        uint2 o;
        o.x = *(unsigned*)&h0; o.y = *(unsigned*)&h1;
        ((uint2*)g_xTh)[i] = o;
    }
}

// Gather: one warp per node, all 4 batches. One packed (src | norm_f16) word
// per edge -> ONE shuffle per edge. Norms pre-zeroed beyond cnt -> the 8-edge
// groups are conditional-free. f32 accumulation, f16 y store.
__global__ void __launch_bounds__(256)
k_gather() {
    int n    = blockIdx.x * 8 + (threadIdx.x >> 5);   // NN % 8 == 0
    int lane = threadIdx.x & 31;

    int   cnt  = g_cnt[n];
    float dinv = rsqrtf((float)(cnt + 1));            // deg = cnt + 1
    const unsigned* brow = g_bkt + (size_t)n * CAP;

    unsigned s0 = (lane < cnt) ? brow[lane] : 0u;     // coalesced 128B
    float   nm0 = (lane < cnt) ? dinv * rsqrtf((float)(g_cnt[s0] + 1)) : 0.f;
    // pack: src in low 16 (NN < 32768), f16 norm in high 16
    unsigned w0 = s0 | ((unsigned)__half_as_ushort(__float2half_rn(nm0)) << 16);

    bool act = lane < 24;
    const uint2* xTq = (const uint2*)g_xTh;

    float4 acc = make_float4(0.f, 0.f, 0.f, 0.f);
    if (act) {
        float4 xs = h4tof4(__ldg(xTq + (size_t)n * 24 + lane));
        float inv = dinv * dinv;                      // self-loop weight 1/deg
        acc.x = xs.x * inv; acc.y = xs.y * inv;
        acc.z = xs.z * inv; acc.w = xs.w * inv;
    }

    if (cnt <= 32) {
        int rc = (cnt + 7) >> 3;                      // 8-edge groups
        for (int g = 0; g < rc; g++) {
            int e = 8 * g;                            // e+i <= 31 for cnt<=32
            unsigned w_[8];
#pragma unroll
            for (int i = 0; i < 8; i++)
                w_[i] = __shfl_sync(0xffffffffu, w0, e + i);
            if (act) {
                uint2 v[8];
#pragma unroll
                for (int i = 0; i < 8; i++)
                    v[i] = __ldg(xTq + (size_t)(w_[i] & 0xFFFFu) * 24 + lane);
#pragma unroll
                for (int i = 0; i < 8; i++) {
                    float nm = __half2float(__ushort_as_half((unsigned short)(w_[i] >> 16)));
                    float4 f = h4tof4(v[i]);
                    acc.x = fmaf(nm, f.x, acc.x);
                    acc.y = fmaf(nm, f.y, acc.y);
                    acc.z = fmaf(nm, f.z, acc.z);
                    acc.w = fmaf(nm, f.w, acc.w);
                }
            }
        }
    } else {
        // Generic fallback (in-degree > 32): lane-uniform per-edge loop.
        for (int e = 0; e < cnt; e++) {
            unsigned c = brow[e];
            float nm = dinv * rsqrtf((float)(g_cnt[c] + 1));
            if (act) {
                float4 f = h4tof4(__ldg(xTq + (size_t)c * 24 + lane));
                acc.x = fmaf(nm, f.x, acc.x); acc.y = fmaf(nm, f.y, acc.y);
                acc.z = fmaf(nm, f.z, acc.z); acc.w = fmaf(nm, f.w, acc.w);
            }
        }
    }
    if (act) {
        int q = lane % 6, b = lane / 6;
        __half2 h0 = __floats2half2_rn(acc.x, acc.y);
        __half2 h1 = __floats2half2_rn(acc.z, acc.w);
        uint2 o; o.x = *(unsigned*)&h0; o.y = *(unsigned*)&h1;
        ((uint2*)g_yh)[((size_t)b * NN + n) * NQ + q] = o;
    }
}

// Pointwise collapse + head GEMV. TWO threads per (b,node): thread r handles
// h-pairs [8r, 8r+8). Partial head GEMV summed via shfl_xor(1); r==0 writes.
// First blocks also re-zero g_cnt for the next graph replay.
__global__ void __launch_bounds__(256)
k_node(const float* __restrict__ hw, const float* __restrict__ hb,
       float* __restrict__ out) {
    __shared__ unsigned s_Mz0[16], s_Mz1[16], s_czp[16];   // half2 per h-pair
    __shared__ unsigned s_Mh0[16], s_Mh1[16], s_chp[16];
    __shared__ u64 s_hwp[NH * NO / 2];
    __shared__ u64 s_hbp[NO / 2];
    __shared__ unsigned s_ph[NT];
    int tid = threadIdx.x;
    int gid2 = blockIdx.x * 256 + tid;

    if (gid2 < NN) g_cnt[gid2] = 0;               // reset for next replay

    if (tid < 16) {
        s_Mz0[tid] = h2u(__floats2half2_rn(g_Mz[2 * tid], g_Mz[2 * tid + 1]));
        s_Mz1[tid] = h2u(__floats2half2_rn(g_Mz[NH + 2 * tid], g_Mz[NH + 2 * tid + 1]));
        s_czp[tid] = h2u(__floats2half2_rn(g_cz[2 * tid], g_cz[2 * tid + 1]));
        s_Mh0[tid] = h2u(__floats2half2_rn(g_Mh[2 * tid], g_Mh[2 * tid + 1]));
        s_Mh1[tid] = h2u(__floats2half2_rn(g_Mh[NH + 2 * tid], g_Mh[NH + 2 * tid + 1]));
        s_chp[tid] = h2u(__floats2half2_rn(g_ch[2 * tid], g_ch[2 * tid + 1]));
    }
    if (tid < NT) s_ph[tid] = h2u(__float2half2_rn(g_p[tid]));
    for (int i = tid; i < NH * NO / 2; i += 256) s_hwp[i] = ((const u64*)hw)[i];
    if (tid < NO / 2) s_hbp[tid] = ((const u64*)hb)[tid];
    __syncthreads();

    if (gid2 >= NODE_THREADS) return;

    int gid = gid2 >> 1;                          // (b,node) id = b*NN + n
    int r   = gid2 & 1;                           // which half of h

    // y row: 24 halfs = 48B = 3 x uint4 (same row read by both threads; L1).
    __half yh[NODE_W];
    const uint4* yq = (const uint4*)g_yh + (size_t)gid * 3;
#pragma unroll
    for (int i = 0; i < 3; i++) {
        uint4 u = __ldg(yq + i);
        *(uint4*)(yh + 8 * i) = u;
    }
    unsigned a2[NT], b2[NT];
#pragma unroll
    for (int t = 0; t < NT; t++) {
        a2[t] = h2u(__half2half2(yh[t]));
        b2[t] = h2u(__half2half2(yh[NT + t]));
    }
    unsigned ph_[NT];
#pragma unroll
    for (int t = 0; t < NT; t++) ph_[t] = s_ph[t];

    u64 o2[NO / 2];
#pragma unroll
    for (int j = 0; j < NO / 2; j++) o2[j] = 0ULL;

    int kbase = r * 8;
#pragma unroll 1
    for (int kk = 0; kk < 8; kk++) {              // this thread's h-pairs
        int k = kbase + kk;
        unsigned mz0 = s_Mz0[k], mz1 = s_Mz1[k], czc = s_czp[k];
        unsigned mh0 = s_Mh0[k], mh1 = s_Mh1[k], chc = s_chp[k];
        unsigned acc = 0;                         // half2 zero
#pragma unroll
        for (int t = 0; t < NT; t++) {
            unsigned azn = hfma2u(a2[t], mz0, hfma2u(b2[t], mz1, czc)); // -(az)/2
            unsigned ahp = hfma2u(a2[t], mh0, hfma2u(b2[t], mh1, chc));
            unsigned tzn = tanh2(azn);            // = -tz (odd fn, consts negated)
            unsigned th  = tanh2(ahp);
            unsigned u   = hfma2u(tzn, th, th);   // (1 - tz) * th
            acc = hfma2u(ph_[t], u, acc);
        }
        __half2 ah2 = *(__half2*)&acc;
        float rl = fmaxf(__low2float(ah2), 0.f);  // relu, h = 2k
        float rh = fmaxf(__high2float(ah2), 0.f); // h = 2k+1
        u64 rl2 = pk(rl, rl), rh2 = pk(rh, rh);
        const u64* w0 = &s_hwp[(2 * k) * (NO / 2)];
        const u64* w1 = &s_hwp[(2 * k + 1) * (NO / 2)];
#pragma unroll
        for (int j = 0; j < NO / 2; j++)
            o2[j] = fma2(rl2, w0[j], fma2(rh2, w1[j], o2[j]));
    }

    // Combine the two halves (adjacent lanes) and write from r == 0.
#pragma unroll
    for (int j = 0; j < NO / 2; j++)
        o2[j] = add2(o2[j], __shfl_xor_sync(0xffffffffu, o2[j], 1));

    if (r == 0) {
        float of[NO];
#pragma unroll
        for (int j = 0; j < NO / 2; j++) {
            u64 v = add2(o2[j], s_hbp[j]);
            upk(v, of[2 * j], of[2 * j + 1]);
        }
        float4* op4 = (float4*)(out + (size_t)gid * NO);
#pragma unroll
        for (int j = 0; j < NO / 4; j++)
            op4[j] = make_float4(of[4 * j], of[4 * j + 1], of[4 * j + 2], of[4 * j + 3]);
    }
}

extern "C" void kernel_launch(void* const* d_in, const int* in_sizes, int n_in,
                              void* d_out, int out_size) {
    const float* x   = (const float*)d_in[0];
    const int*   ei  = (const int*)d_in[1];
    const float* att = (const float*)d_in[2];
    const float* czw = (const float*)d_in[3];
    const float* czb = (const float*)d_in[4];
    const float* lzw = (const float*)d_in[5];
    const float* lzb = (const float*)d_in[6];
    // d_in[7..10] = conv_r_*, lin_r_* : dead (H0 == 0 -> H0*R == 0)
    const float* chw = (const float*)d_in[11];
    const float* chb = (const float*)d_in[12];
    const float* lhw = (const float*)d_in[13];
    const float* lhb = (const float*)d_in[14];
    const float* hw  = (const float*)d_in[15];
    const float* hb  = (const float*)d_in[16];
    float* out = (float*)d_out;

    // Host-side resources created once on the first (uncaptured correctness)
    // call. Device work per call is identical -> deterministic & capturable.
    static cudaStream_t sB = nullptr;
    static cudaEvent_t eF = nullptr, eB = nullptr;
    if (sB == nullptr) {
        cudaStreamCreateWithFlags(&sB, cudaStreamNonBlocking);
        cudaEventCreateWithFlags(&eF, cudaEventDisableTiming);
        cudaEventCreateWithFlags(&eB, cudaEventDisableTiming);
    }

    // Fork: bring the transpose stream into the capture graph.
    cudaEventRecord(eF, 0);
    cudaStreamWaitEvent(sB, eF, 0);

    k_fillw<<<FILL_BLOCKS + 1, 256>>>(ei, att, czw, czb, lzw, lzb,
                                      chw, chb, lhw, lhb);  // stream 0
    k_trans<<<TR_BLOCKS, 256, 0, sB>>>(x);                  // stream B

    // Join B before gather (needs buckets + f16 xT).
    cudaEventRecord(eB, sB);
    cudaStreamWaitEvent(0, eB, 0);
    k_gather<<<NN / 8, 256>>>();

    k_node<<<(NODE_THREADS + 255) / 256, 256>>>(hw, hb, out);
}